// round 11
// baseline (speedup 1.0000x reference)
#include <cuda_runtime.h>
#include <cstdint>
#include <math.h>

// Problem constants
#define HH    200
#define WW    200
#define HWSZ  40000
#define CIN   256
#define BB    2
#define CG    64      // channels per group (both real DCN groups and conv pseudo-groups)
#define NGK   36      // 4 groups * 9 taps
#define OMCH  108     // offset-mask conv output channels

// Scratch (static device arrays -- no runtime allocation)
__device__ float g_om[BB * OMCH * HWSZ];          // 34.56 MB: conv output (raw, pre-sigmoid)
__device__ float g_wt_dcn[NGK * CG * 256];        // 2.36 MB: w_dcn transposed [gk][cg][oc]
__device__ float g_wt_om[NGK * CG * 128];         // 1.18 MB: w_om transposed, oc padded to 128

typedef unsigned long long ull;

__device__ __forceinline__ ull fdup(float x) {
    ull r; asm("mov.b64 %0, {%1, %1};" : "=l"(r) : "f"(x)); return r;
}
__device__ __forceinline__ void fma2(ull& d, ull a, ull b) {
    // d = a*b + d, packed 2x fp32 (Blackwell f32x2 pipe: 2 FMA per FFMA2 issue)
    asm("fma.rn.f32x2 %0, %1, %2, %0;" : "+l"(d) : "l"(a), "l"(b));
}
__device__ __forceinline__ float2 unpk(ull a) {
    float2 r; asm("mov.b64 {%0, %1}, %2;" : "=f"(r.x), "=f"(r.y) : "l"(a)); return r;
}

// ---------------------------------------------------------------------------
// Weight transposes: [O][C][9] -> [gk][cg][oc] (oc contiguous => coalesced
// smem tile fills in the GEMM kernel).
// ---------------------------------------------------------------------------
__global__ void k_transpose_dcn(const float* __restrict__ w, float* __restrict__ wt) {
    int tid = blockIdx.x * 256 + threadIdx.x;
    if (tid >= NGK * CG * 256) return;
    int o  = tid & 255;
    int cg = (tid >> 8) & 63;
    int gk = tid >> 14;
    int g = gk / 9, k = gk - g * 9;
    wt[tid] = w[(o * CIN + g * CG + cg) * 9 + k];
}

__global__ void k_transpose_om(const float* __restrict__ w, float* __restrict__ wt) {
    int tid = blockIdx.x * 256 + threadIdx.x;
    if (tid >= NGK * CG * 128) return;
    int o  = tid & 127;
    int cg = (tid >> 7) & 63;
    int gk = tid >> 13;
    int g = gk / 9, k = gk - g * 9;
    wt[tid] = (o < OMCH) ? w[(o * CIN + g * CG + cg) * 9 + k] : 0.0f;
}

// ---------------------------------------------------------------------------
// Unified gather + GEMM kernel.
//   Tile: OCT output channels x 64 consecutive pixels (linear over B*H*W;
//         80000 % 64 == 0 and the batch boundary (40000) is tile-aligned).
//   256 threads: to = t / PIX_THR handles 8 oc (4 f32x2 pairs),
//                tp = t % PIX_THR handles PIX_PER = 64/PIX_THR pixels.
//   Per (g,k) iteration:
//     - per-pixel sampling meta in registers (pix = t & 63, 4x redundant)
//     - W tile [64 cg][OCT] -> smem (coalesced from transposed weights)
//     - gather v[64 cg][64 px] -> smem as duplicated float2 (broadcast operand
//       pre-packed => inner loop has zero mov.b64)
//     - register-tile GEMM with fma.rn.f32x2 (acc pairs along oc)
//   DEFORM=true : bilinear sample with offsets/sigmoid(mask) from g_om, ReLU.
//   DEFORM=false: identity 3x3 taps (the offset-mask conv itself), +bias.
// ---------------------------------------------------------------------------
template <int OCT, int PIX_THR, bool DEFORM, int MAXB>
__global__ void __launch_bounds__(256, MAXB)
k_fused(const float* __restrict__ x, const float* __restrict__ wt,
        const float* __restrict__ om, const float* __restrict__ bias,
        float* __restrict__ out, int o_valid)
{
    constexpr int PIX_PER = 64 / PIX_THR;
    extern __shared__ float smem[];
    float*  sWt  = smem;                           // 64 * OCT floats
    float2* vdup = (float2*)(smem + 64 * OCT);     // 64 * 64 float2 (duplicated)

    const int t   = threadIdx.x;
    const int tp  = t % PIX_THR;
    const int to  = t / PIX_THR;
    const int pix = t & 63;

    const int p0 = blockIdx.x * 64;
    const int b  = (p0 >= HWSZ) ? 1 : 0;
    const int hw = p0 - b * HWSZ + pix;
    const int h  = hw / WW;
    const int w  = hw - h * WW;

    ull acc[4][PIX_PER];
#pragma unroll
    for (int i = 0; i < 4; i++)
#pragma unroll
        for (int j = 0; j < PIX_PER; j++) acc[i][j] = 0ull;

    const int xgbase = b * CIN * HWSZ;
    const int ombase = b * OMCH * HWSZ + hw;

    for (int gk = 0; gk < NGK; gk++) {
        const int g  = gk / 9;
        const int k  = gk - g * 9;
        const int ki = k / 3;
        const int kj = k - ki * 3;

        // ---- per-pixel sampling metadata (registers) ----
        int   a00 = 0, a01 = 0, a10 = 0, a11 = 0;
        float w00, w01 = 0.f, w10 = 0.f, w11 = 0.f;
        if (DEFORM) {
            float dy = om[ombase + (g * 18 + 2 * k)     * HWSZ];
            float dx = om[ombase + (g * 18 + 2 * k + 1) * HWSZ];
            float mr = om[ombase + (72 + g * 9 + k)     * HWSZ];
            float m  = 1.0f / (1.0f + expf(-mr));
            float py = (float)(h - 1 + ki) + dy;
            float px = (float)(w - 1 + kj) + dx;
            float fy = floorf(py), fx = floorf(px);
            int   y0 = (int)fy,    x0 = (int)fx;
            float wy = py - fy,    wx = px - fx;
            bool vy0 = (unsigned)y0       < HH, vy1 = (unsigned)(y0 + 1) < HH;
            bool vx0 = (unsigned)x0       < WW, vx1 = (unsigned)(x0 + 1) < WW;
            float oy = 1.0f - wy, ox = 1.0f - wx;
            w00 = (vy0 && vx0) ? m * oy * ox : 0.0f;
            w01 = (vy0 && vx1) ? m * oy * wx : 0.0f;
            w10 = (vy1 && vx0) ? m * wy * ox : 0.0f;
            w11 = (vy1 && vx1) ? m * wy * wx : 0.0f;
            int cy0 = min(max(y0, 0), HH - 1), cy1 = min(max(y0 + 1, 0), HH - 1);
            int cx0 = min(max(x0, 0), WW - 1), cx1 = min(max(x0 + 1, 0), WW - 1);
            a00 = cy0 * WW + cx0; a01 = cy0 * WW + cx1;
            a10 = cy1 * WW + cx0; a11 = cy1 * WW + cx1;
        } else {
            int y0 = h - 1 + ki, x0 = w - 1 + kj;
            bool inb = ((unsigned)y0 < HH) && ((unsigned)x0 < WW);
            w00 = inb ? 1.0f : 0.0f;
            a00 = min(max(y0, 0), HH - 1) * WW + min(max(x0, 0), WW - 1);
        }

        // ---- W tile -> smem (coalesced float4) ----
        {
            const float4* src = (const float4*)(wt + gk * 64 * OCT);
            float4*       dst = (float4*)sWt;
#pragma unroll
            for (int j = 0; j < (64 * OCT) / (4 * 256); j++)
                dst[t + j * 256] = src[t + j * 256];
        }

        // ---- gather v[cg][pix] (thread owns fixed pix, strides cg by 4) ----
        {
            const float* pl = x + xgbase + (g * CG + (t >> 6)) * HWSZ;
#pragma unroll
            for (int e = 0; e < 16; e++) {
                float val;
                if (DEFORM) {
                    val = w00 * pl[a00] + w01 * pl[a01]
                        + w10 * pl[a10] + w11 * pl[a11];
                } else {
                    val = w00 * pl[a00];
                }
                vdup[((t >> 6) + 4 * e) * 64 + pix] = make_float2(val, val);
                pl += 4 * HWSZ;
            }
        }
        __syncthreads();

        // ---- register-tile GEMM: out[8 oc][PIX_PER px] += W[.][cg] * v[cg][.] ----
#pragma unroll 4
        for (int cg = 0; cg < 64; cg++) {
            const ulonglong2* wr = (const ulonglong2*)(sWt + cg * OCT + to * 8);
            ulonglong2 wa = wr[0];
            ulonglong2 wb = wr[1];
            const ulonglong2* vr = (const ulonglong2*)(vdup + cg * 64 + tp * PIX_PER);
#pragma unroll
            for (int q = 0; q < PIX_PER / 2; q++) {
                ulonglong2 vv = vr[q];
                fma2(acc[0][2 * q],     wa.x, vv.x);
                fma2(acc[0][2 * q + 1], wa.x, vv.y);
                fma2(acc[1][2 * q],     wa.y, vv.x);
                fma2(acc[1][2 * q + 1], wa.y, vv.y);
                fma2(acc[2][2 * q],     wb.x, vv.x);
                fma2(acc[2][2 * q + 1], wb.x, vv.y);
                fma2(acc[3][2 * q],     wb.y, vv.x);
                fma2(acc[3][2 * q + 1], wb.y, vv.y);
            }
        }
        __syncthreads();
    }

    // ---- epilogue: unpack f32x2, bias/ReLU, vectorized coalesced stores ----
    const int hwS = (p0 - b * HWSZ) + tp * PIX_PER;
#pragma unroll
    for (int pi = 0; pi < 4; pi++) {
        float v0[PIX_PER], v1[PIX_PER];
#pragma unroll
        for (int j = 0; j < PIX_PER; j++) {
            float2 u = unpk(acc[pi][j]);
            v0[j] = u.x; v1[j] = u.y;
        }
#pragma unroll
        for (int half = 0; half < 2; half++) {
            int o = to * 8 + pi * 2 + half;
            if (o < o_valid) {
                float bv = 0.0f;
                if (!DEFORM) bv = bias[o];
                float* op = out + (size_t)(b * o_valid + o) * HWSZ + hwS;
                const float* vv = half ? v1 : v0;
#pragma unroll
                for (int q = 0; q < PIX_PER / 4; q++) {
                    float4 r;
                    r.x = vv[4 * q + 0] + bv;
                    r.y = vv[4 * q + 1] + bv;
                    r.z = vv[4 * q + 2] + bv;
                    r.w = vv[4 * q + 3] + bv;
                    if (DEFORM) {
                        r.x = fmaxf(r.x, 0.0f); r.y = fmaxf(r.y, 0.0f);
                        r.z = fmaxf(r.z, 0.0f); r.w = fmaxf(r.w, 0.0f);
                    }
                    ((float4*)op)[q] = r;
                }
            }
        }
    }
}

// ---------------------------------------------------------------------------
extern "C" void kernel_launch(void* const* d_in, const int* in_sizes, int n_in,
                              void* d_out, int out_size)
{
    const float* x     = (const float*)d_in[0];   // [2,256,200,200]
    const float* w_om  = (const float*)d_in[1];   // [108,256,3,3]
    const float* b_om  = (const float*)d_in[2];   // [108]
    const float* w_dcn = (const float*)d_in[3];   // [256,256,3,3]
    float* out = (float*)d_out;                   // [2,256,200,200]

    float *om, *wtd, *wto;
    cudaGetSymbolAddress((void**)&om,  g_om);
    cudaGetSymbolAddress((void**)&wtd, g_wt_dcn);
    cudaGetSymbolAddress((void**)&wto, g_wt_om);

    const int smem_conv = 64 * 128 * 4 + 64 * 64 * 8;   // 65536
    const int smem_dcn  = 64 * 256 * 4 + 64 * 64 * 8;   // 98304
    cudaFuncSetAttribute(k_fused<128, 16, false, 3>,
                         cudaFuncAttributeMaxDynamicSharedMemorySize, smem_conv);
    cudaFuncSetAttribute(k_fused<256, 8, true, 2>,
                         cudaFuncAttributeMaxDynamicSharedMemorySize, smem_dcn);

    // weight transposes (independent, tiny)
    k_transpose_dcn<<<2304, 256>>>(w_dcn, wtd);
    k_transpose_om<<<1152, 256>>>(w_om, wto);

    // offset-mask conv: om = conv3x3(x, w_om) + b_om   (raw; sigmoid applied on read)
    k_fused<128, 16, false, 3><<<1250, 256, smem_conv>>>(x, wto, nullptr, b_om, om, OMCH);

    // modulated deformable conv + ReLU
    k_fused<256, 8, true, 2><<<1250, 256, smem_dcn>>>(x, wtd, om, nullptr, out, 256);
}